// round 2
// baseline (speedup 1.0000x reference)
#include <cuda_runtime.h>
#include <math.h>

#define BB      32
#define CC      384
#define SIDE    56
#define HWD     3136          // 56*56
#define TOKENS  100352        // 32*3136
#define NHEADS  12
#define HEADD   32
#define NWIN    2048          // 32 * 8 * 8
#define HIDDEN  1536
#define QKVN    1152
#define LN_EPS  1e-5f
#define ATT_SCALE 0.17677669529663687f  // 32^-0.5

// ---------------- scratch (static device allocations; no cudaMalloc) -------
__device__ float g_mean[TOKENS];
__device__ float g_rstd[TOKENS];
__device__ float g_qkv[(size_t)TOKENS * QKVN];    // 462 MB
__device__ float g_att[(size_t)TOKENS * CC];      // 154 MB
__device__ float g_seq1[(size_t)TOKENS * CC];     // 154 MB
__device__ float g_seq2[(size_t)TOKENS * CC];     // 154 MB
__device__ float g_hid[(size_t)TOKENS * HIDDEN];  // 616 MB

// ---------------- LayerNorm statistics (mean, rstd per token) --------------
__global__ void ln_stats_kernel(const float* __restrict__ x) {
    int blk = blockIdx.x;              // 0..1567
    int b   = blk / (HWD / 64);
    int hw0 = (blk % (HWD / 64)) * 64;
    int t   = threadIdx.x & 63;        // token within tile
    int cg  = threadIdx.x >> 6;        // channel group 0..3
    const float* xp = x + (size_t)b * CC * HWD + hw0 + t;
    float s = 0.f, ss = 0.f;
    for (int c = cg; c < CC; c += 4) {
        float v = xp[(size_t)c * HWD];
        s += v; ss += v * v;
    }
    __shared__ float sh[2][4][64];
    sh[0][cg][t] = s; sh[1][cg][t] = ss;
    __syncthreads();
    if (cg == 0) {
        float S  = sh[0][0][t] + sh[0][1][t] + sh[0][2][t] + sh[0][3][t];
        float SS = sh[1][0][t] + sh[1][1][t] + sh[1][2][t] + sh[1][3][t];
        float mu  = S * (1.0f / CC);
        float var = SS * (1.0f / CC) - mu * mu;
        int g = b * HWD + hw0 + t;
        g_mean[g] = mu;
        g_rstd[g] = rsqrtf(var + LN_EPS);
    }
}

// ---------------- fused tiled SGEMM: Y = A @ W^T + bias (+ epilogue) -------
// MODE 0: A = LayerNorm(x) fused on load (x is NCHW)      -> g_qkv
// MODE 1: A = g_att, epilogue += shortcut x (NCHW)        -> g_seq1
// MODE 2: A = g_seq2, epilogue exact GELU                 -> g_hid
// MODE 3: A = g_hid,  epilogue += g_seq2, write NCHW out  -> out
template<int MODE>
__global__ __launch_bounds__(256) void gemm_kernel(
    const float* __restrict__ x,
    const float* __restrict__ Wt,     // [N][K] row-major
    const float* __restrict__ bias,   // [N]
    const float* __restrict__ lng,
    const float* __restrict__ lnb,
    float* __restrict__ out)
{
    constexpr int K = (MODE == 3) ? HIDDEN : CC;
    const int m0 = blockIdx.y * 128;
    const int n0 = blockIdx.x * 128;
    const int tid = threadIdx.x;

    __shared__ float As[16][132];
    __shared__ float Bs[16][132];

    float acc[8][8];
    #pragma unroll
    for (int i = 0; i < 8; i++)
        #pragma unroll
        for (int j = 0; j < 8; j++) acc[i][j] = 0.f;

    const int lr = tid & 127;
    const int lk = tid >> 7;
    const float* xr = nullptr;
    float mu = 0.f, rs = 0.f;
    if constexpr (MODE == 0) {
        int gm = m0 + lr;
        int bb = gm / HWD, hw = gm % HWD;
        xr = x + (size_t)bb * CC * HWD + hw;
        mu = g_mean[gm]; rs = g_rstd[gm];
    }
    const float* Arow = nullptr;
    if constexpr (MODE == 1) Arow = g_att;
    if constexpr (MODE == 2) Arow = g_seq2;
    if constexpr (MODE == 3) Arow = g_hid;

    const int a_k4 = tid & 3, a_r = tid >> 2;
    const int b_k4 = tid & 3, b_n = tid >> 2;

    for (int k0 = 0; k0 < K; k0 += 16) {
        if constexpr (MODE == 0) {
            #pragma unroll
            for (int i = 0; i < 8; i++) {
                int kk = lk + 2 * i;
                int k = k0 + kk;
                float v = xr[(size_t)k * HWD];
                As[kk][lr] = (v - mu) * rs * __ldg(&lng[k]) + __ldg(&lnb[k]);
            }
        } else {
            #pragma unroll
            for (int rr = 0; rr < 2; rr++) {
                int r = a_r + rr * 64;
                float4 v = *(const float4*)(Arow + (size_t)(m0 + r) * K + k0 + a_k4 * 4);
                As[a_k4 * 4 + 0][r] = v.x;
                As[a_k4 * 4 + 1][r] = v.y;
                As[a_k4 * 4 + 2][r] = v.z;
                As[a_k4 * 4 + 3][r] = v.w;
            }
        }
        #pragma unroll
        for (int rr = 0; rr < 2; rr++) {
            int n = b_n + rr * 64;
            float4 v = *(const float4*)(Wt + (size_t)(n0 + n) * K + k0 + b_k4 * 4);
            Bs[b_k4 * 4 + 0][n] = v.x;
            Bs[b_k4 * 4 + 1][n] = v.y;
            Bs[b_k4 * 4 + 2][n] = v.z;
            Bs[b_k4 * 4 + 3][n] = v.w;
        }
        __syncthreads();

        const int ty = tid >> 4, tx = tid & 15;
        #pragma unroll
        for (int k = 0; k < 16; k++) {
            float a[8], b[8];
            *(float4*)(a)     = *(const float4*)&As[k][ty * 8];
            *(float4*)(a + 4) = *(const float4*)&As[k][ty * 8 + 4];
            *(float4*)(b)     = *(const float4*)&Bs[k][tx * 8];
            *(float4*)(b + 4) = *(const float4*)&Bs[k][tx * 8 + 4];
            #pragma unroll
            for (int i = 0; i < 8; i++)
                #pragma unroll
                for (int j = 0; j < 8; j++)
                    acc[i][j] = fmaf(a[i], b[j], acc[i][j]);
        }
        __syncthreads();
    }

    const int ty = tid >> 4, tx = tid & 15;
    #pragma unroll
    for (int i = 0; i < 8; i++) {
        int m = m0 + ty * 8 + i;
        int bb = 0, hw = 0;
        if constexpr (MODE == 1 || MODE == 3) { bb = m / HWD; hw = m % HWD; }
        #pragma unroll
        for (int j = 0; j < 8; j++) {
            int n = n0 + tx * 8 + j;
            float v = acc[i][j] + __ldg(&bias[n]);
            if constexpr (MODE == 0) {
                g_qkv[(size_t)m * QKVN + n] = v;
            } else if constexpr (MODE == 1) {
                v += x[(size_t)bb * CC * HWD + (size_t)n * HWD + hw];
                g_seq1[(size_t)m * CC + n] = v;
            } else if constexpr (MODE == 2) {
                float g = 0.5f * v * (1.0f + erff(v * 0.70710678118654752f));
                g_hid[(size_t)m * HIDDEN + n] = g;
            } else {
                v += g_seq2[(size_t)m * CC + n];
                out[(size_t)bb * CC * HWD + (size_t)n * HWD + hw] = v;
            }
        }
    }
}

// ---------------- windowed attention: one block per (window, head) ---------
__global__ __launch_bounds__(256) void attn_kernel(const float* __restrict__ bias_table) {
    int wh = blockIdx.x;
    int w  = wh / NHEADS;
    int h  = wh - w * NHEADS;
    int b  = w >> 6;
    int wr = w & 63;
    int nh = wr >> 3, nw = wr & 7;
    int tid = threadIdx.x;

    // NOTE: ss rows hold 49 scores -> stride 52 (R1 bug: stride 33 overran rows
    // and corrupted gtok -> IMA)
    __shared__ float qs[49][33], ks[49][33], vs[49][33];
    __shared__ float ss[49][52];
    __shared__ int gtok[49];
    if (tid < 49) {
        int i = tid / 7, j = tid - i * 7;
        gtok[tid] = b * HWD + (nh * 7 + i) * SIDE + (nw * 7 + j);
    }
    __syncthreads();

    for (int idx = tid; idx < 49 * 32; idx += 256) {
        int n = idx >> 5, d = idx & 31;
        size_t base = (size_t)gtok[n] * QKVN + h * HEADD + d;
        qs[n][d] = g_qkv[base];
        ks[n][d] = g_qkv[base + 384];
        vs[n][d] = g_qkv[base + 768];
    }
    __syncthreads();

    for (int idx = tid; idx < 49 * 49; idx += 256) {
        int n = idx / 49, m = idx - n * 49;
        float a = 0.f;
        #pragma unroll
        for (int d = 0; d < 32; d++) a = fmaf(qs[n][d], ks[m][d], a);
        int i1 = n / 7, j1 = n - i1 * 7;
        int i2 = m / 7, j2 = m - i2 * 7;
        int ridx = (i1 - i2 + 6) * 13 + (j1 - j2 + 6);
        ss[n][m] = a * ATT_SCALE + __ldg(&bias_table[ridx * NHEADS + h]);
    }
    __syncthreads();

    int warp = tid >> 5, lane = tid & 31;
    for (int n = warp; n < 49; n += 8) {
        float e0 = ss[n][lane];
        float e1 = (lane + 32 < 49) ? ss[n][lane + 32] : -1e30f;
        float mx = fmaxf(e0, e1);
        #pragma unroll
        for (int o = 16; o; o >>= 1) mx = fmaxf(mx, __shfl_xor_sync(0xffffffffu, mx, o));
        float x0 = __expf(e0 - mx);
        float x1 = (lane + 32 < 49) ? __expf(e1 - mx) : 0.f;
        float sm = x0 + x1;
        #pragma unroll
        for (int o = 16; o; o >>= 1) sm += __shfl_xor_sync(0xffffffffu, sm, o);
        float inv = 1.0f / sm;
        ss[n][lane] = x0 * inv;
        if (lane + 32 < 49) ss[n][lane + 32] = x1 * inv;
    }
    __syncthreads();

    for (int idx = tid; idx < 49 * 32; idx += 256) {
        int n = idx >> 5, d = idx & 31;
        float a = 0.f;
        #pragma unroll
        for (int m = 0; m < 49; m++) a = fmaf(ss[n][m], vs[m][d], a);
        g_att[(size_t)gtok[n] * CC + h * HEADD + d] = a;
    }
}

// ---------------- depthwise 3x3 conv + BN (inference) ----------------------
__global__ void conv_bn_kernel(const float* __restrict__ conv_w,
                               const float* __restrict__ bn_g,
                               const float* __restrict__ bn_b,
                               const float* __restrict__ bn_mean,
                               const float* __restrict__ bn_var) {
    int idx = blockIdx.x * 256 + threadIdx.x;
    if (idx >= TOKENS * CC) return;
    int c   = idx % CC;
    int tok = idx / CC;
    int b   = tok / HWD;
    int hw  = tok - b * HWD;
    int h   = hw / SIDE, w = hw - h * SIDE;
    float acc = 0.f;
    #pragma unroll
    for (int dy = 0; dy < 3; dy++) {
        int y = h + dy - 1;
        if (y < 0 || y >= SIDE) continue;
        #pragma unroll
        for (int dx = 0; dx < 3; dx++) {
            int xx = w + dx - 1;
            if (xx < 0 || xx >= SIDE) continue;
            acc = fmaf(g_seq1[(size_t)(b * HWD + y * SIDE + xx) * CC + c],
                       __ldg(&conv_w[c * 9 + dy * 3 + dx]), acc);
        }
    }
    float sc = __ldg(&bn_g[c]) * rsqrtf(__ldg(&bn_var[c]) + LN_EPS);
    g_seq2[idx] = (acc - __ldg(&bn_mean[c])) * sc + __ldg(&bn_b[c]);
}

// ---------------------------------------------------------------------------
extern "C" void kernel_launch(void* const* d_in, const int* in_sizes, int n_in,
                              void* d_out, int out_size) {
    const float* x          = (const float*)d_in[0];
    const float* ln_g       = (const float*)d_in[1];
    const float* ln_b       = (const float*)d_in[2];
    const float* qkv_w      = (const float*)d_in[3];
    const float* qkv_b      = (const float*)d_in[4];
    const float* proj_w     = (const float*)d_in[5];
    const float* proj_b     = (const float*)d_in[6];
    const float* bias_table = (const float*)d_in[7];
    const float* conv_w     = (const float*)d_in[8];
    const float* bn_g       = (const float*)d_in[9];
    const float* bn_b       = (const float*)d_in[10];
    const float* bn_mean    = (const float*)d_in[11];
    const float* bn_var     = (const float*)d_in[12];
    const float* w1         = (const float*)d_in[13];
    const float* b1         = (const float*)d_in[14];
    const float* w2         = (const float*)d_in[15];
    const float* b2         = (const float*)d_in[16];
    float* out = (float*)d_out;

    ln_stats_kernel<<<TOKENS / 64, 256>>>(x);
    gemm_kernel<0><<<dim3(QKVN / 128, TOKENS / 128), 256>>>(x, qkv_w, qkv_b, ln_g, ln_b, nullptr);
    attn_kernel<<<NWIN * NHEADS, 256>>>(bias_table);
    gemm_kernel<1><<<dim3(CC / 128, TOKENS / 128), 256>>>(x, proj_w, proj_b, nullptr, nullptr, nullptr);
    conv_bn_kernel<<<(TOKENS * CC + 255) / 256, 256>>>(conv_w, bn_g, bn_b, bn_mean, bn_var);
    gemm_kernel<2><<<dim3(HIDDEN / 128, TOKENS / 128), 256>>>(nullptr, w1, b1, nullptr, nullptr, nullptr);
    gemm_kernel<3><<<dim3(CC / 128, TOKENS / 128), 256>>>(nullptr, w2, b2, nullptr, nullptr, out);
}

// round 3
// speedup vs baseline: 1.9877x; 1.9877x over previous
#include <cuda_runtime.h>
#include <math.h>
#include <stdint.h>

#define CC      384
#define SIDE    56
#define HWD     3136
#define TOKENS  100352
#define NHEADS  12
#define HEADD   32
#define NWIN    2048
#define HIDDEN  1536
#define QKVN    1152
#define LN_EPS  1e-5f
#define ATT_SCALE 0.17677669529663687f

// ---------------- scratch ----------------
__device__ float g_mean[TOKENS];
__device__ float g_rstd[TOKENS];
__device__ float g_qkv[(size_t)TOKENS * QKVN];
__device__ float g_att[(size_t)TOKENS * CC];
__device__ float g_seq1[(size_t)TOKENS * CC];
__device__ float g_seq2[(size_t)TOKENS * CC];
__device__ float g_hid[(size_t)TOKENS * HIDDEN];

__device__ __forceinline__ uint32_t f2tf(float f) {
    uint32_t u;
    asm("cvt.rna.tf32.f32 %0, %1;" : "=r"(u) : "f"(f));
    return u;
}

__device__ __forceinline__ void mma_tf32(float* d, const uint32_t* a, const uint32_t* b) {
    asm volatile(
        "mma.sync.aligned.m16n8k8.row.col.f32.tf32.tf32.f32 "
        "{%0,%1,%2,%3},{%4,%5,%6,%7},{%8,%9},{%0,%1,%2,%3};"
        : "+f"(d[0]), "+f"(d[1]), "+f"(d[2]), "+f"(d[3])
        : "r"(a[0]), "r"(a[1]), "r"(a[2]), "r"(a[3]), "r"(b[0]), "r"(b[1]));
}

// ---------------- LayerNorm statistics --------------
__global__ void ln_stats_kernel(const float* __restrict__ x) {
    int blk = blockIdx.x;
    int b   = blk / (HWD / 64);
    int hw0 = (blk % (HWD / 64)) * 64;
    int t   = threadIdx.x & 63;
    int cg  = threadIdx.x >> 6;
    const float* xp = x + (size_t)b * CC * HWD + hw0 + t;
    float s = 0.f, ss = 0.f;
    for (int c = cg; c < CC; c += 4) {
        float v = xp[(size_t)c * HWD];
        s += v; ss += v * v;
    }
    __shared__ float sh[2][4][64];
    sh[0][cg][t] = s; sh[1][cg][t] = ss;
    __syncthreads();
    if (cg == 0) {
        float S  = sh[0][0][t] + sh[0][1][t] + sh[0][2][t] + sh[0][3][t];
        float SS = sh[1][0][t] + sh[1][1][t] + sh[1][2][t] + sh[1][3][t];
        float mu  = S * (1.0f / CC);
        float var = SS * (1.0f / CC) - mu * mu;
        int g = b * HWD + hw0 + t;
        g_mean[g] = mu;
        g_rstd[g] = rsqrtf(var + LN_EPS);
    }
}

// ---------------- tf32 tensor-core GEMM: Y = A @ W^T + bias (+ epilogue) ---
// MODE 0: A = LayerNorm(x) (x NCHW) -> g_qkv (row-major)
// MODE 1: A = g_att, += shortcut x (NCHW read) -> g_seq1 (row-major)
// MODE 2: A = g_seq2, GELU -> g_hid (row-major)
// MODE 3: A = g_hid, += g_seq2, -> out (NCHW write)
template<int MODE>
__global__ __launch_bounds__(256) void mma_gemm(
    const float* __restrict__ x,
    const float* __restrict__ Wt,     // [N][K] row-major
    const float* __restrict__ bias,
    const float* __restrict__ lng,
    const float* __restrict__ lnb,
    float* __restrict__ out)
{
    constexpr int K  = (MODE == 3) ? HIDDEN : CC;
    constexpr int KT = K / 16;
    const int m0  = blockIdx.y * 128;
    const int n0  = blockIdx.x * 128;
    const int tid = threadIdx.x;
    const int lane = tid & 31, warp = tid >> 5;
    const int wr = warp >> 2, wc = warp & 3;      // warp tile: 64x32
    const int g  = lane >> 2, c = lane & 3;

    __shared__ uint32_t sm[8512];
    // As buf s: sm[s*2112 + k*132 + m], Bs buf s: sm[4224 + s*2112 + k*132 + n]
    float* Cs = (float*)sm;                        // [64][133] epilogue staging

    float acc[4][4][4];
    #pragma unroll
    for (int i = 0; i < 4; i++)
        #pragma unroll
        for (int j = 0; j < 4; j++)
            #pragma unroll
            for (int q = 0; q < 4; q++) acc[i][j][q] = 0.f;

    // ---- A-source setup ----
    const float* Arow = nullptr;
    if constexpr (MODE == 1) Arow = g_att;
    if constexpr (MODE == 2) Arow = g_seq2;
    if constexpr (MODE == 3) Arow = g_hid;

    const int lr  = tid & 127;   // MODE0 row
    const int lkp = tid >> 7;    // MODE0 k phase
    const float* xr = nullptr;
    float mu = 0.f, rsd = 0.f;
    if constexpr (MODE == 0) {
        int gm = m0 + lr;
        int bb = gm / HWD, hw = gm % HWD;
        xr = x + (size_t)bb * CC * HWD + hw;
        mu = g_mean[gm]; rsd = g_rstd[gm];
    }
    const int a_k4 = tid & 3, a_r = tid >> 2;    // row-major A load map
    const int b_k4 = tid & 3, b_n = tid >> 2;    // W load map

    float fA[8];          // staged A values (8 floats covers both layouts)
    float4 fB0, fB1;      // staged W values

    auto fetch = [&](int kt) {
        int k0 = kt * 16;
        if constexpr (MODE == 0) {
            #pragma unroll
            for (int i = 0; i < 8; i++)
                fA[i] = xr[(size_t)(k0 + lkp + 2 * i) * HWD];
        } else {
            float4 v0 = *(const float4*)(Arow + (size_t)(m0 + a_r) * K + k0 + a_k4 * 4);
            float4 v1 = *(const float4*)(Arow + (size_t)(m0 + a_r + 64) * K + k0 + a_k4 * 4);
            fA[0] = v0.x; fA[1] = v0.y; fA[2] = v0.z; fA[3] = v0.w;
            fA[4] = v1.x; fA[5] = v1.y; fA[6] = v1.z; fA[7] = v1.w;
        }
        fB0 = *(const float4*)(Wt + (size_t)(n0 + b_n) * K + k0 + b_k4 * 4);
        fB1 = *(const float4*)(Wt + (size_t)(n0 + b_n + 64) * K + k0 + b_k4 * 4);
    };
    auto sts = [&](int s, int kt) {
        uint32_t* A = sm + s * 2112;
        uint32_t* B = sm + 4224 + s * 2112;
        if constexpr (MODE == 0) {
            int k0 = kt * 16;
            #pragma unroll
            for (int i = 0; i < 8; i++) {
                int kk = lkp + 2 * i;
                int k = k0 + kk;
                A[kk * 132 + lr] = f2tf((fA[i] - mu) * rsd * __ldg(&lng[k]) + __ldg(&lnb[k]));
            }
        } else {
            #pragma unroll
            for (int q = 0; q < 4; q++) {
                A[(a_k4 * 4 + q) * 132 + a_r]      = f2tf(fA[q]);
                A[(a_k4 * 4 + q) * 132 + a_r + 64] = f2tf(fA[4 + q]);
            }
        }
        float vb0[4] = {fB0.x, fB0.y, fB0.z, fB0.w};
        float vb1[4] = {fB1.x, fB1.y, fB1.z, fB1.w};
        #pragma unroll
        for (int q = 0; q < 4; q++) {
            B[(b_k4 * 4 + q) * 132 + b_n]      = f2tf(vb0[q]);
            B[(b_k4 * 4 + q) * 132 + b_n + 64] = f2tf(vb1[q]);
        }
    };
    auto compute = [&](int s) {
        const uint32_t* A = sm + s * 2112;
        const uint32_t* B = sm + 4224 + s * 2112;
        #pragma unroll
        for (int h = 0; h < 2; h++) {
            int kk = h * 8;
            uint32_t af[4][4], bf[4][2];
            #pragma unroll
            for (int mi = 0; mi < 4; mi++) {
                int mrow = wr * 64 + mi * 16 + g;
                af[mi][0] = A[(kk + c) * 132 + mrow];
                af[mi][1] = A[(kk + c) * 132 + mrow + 8];
                af[mi][2] = A[(kk + c + 4) * 132 + mrow];
                af[mi][3] = A[(kk + c + 4) * 132 + mrow + 8];
            }
            #pragma unroll
            for (int ni = 0; ni < 4; ni++) {
                int ncol = wc * 32 + ni * 8 + g;
                bf[ni][0] = B[(kk + c) * 132 + ncol];
                bf[ni][1] = B[(kk + c + 4) * 132 + ncol];
            }
            #pragma unroll
            for (int mi = 0; mi < 4; mi++)
                #pragma unroll
                for (int ni = 0; ni < 4; ni++)
                    mma_tf32(acc[mi][ni], af[mi], bf[ni]);
        }
    };

    // ---- mainloop (double-buffered) ----
    fetch(0); sts(0, 0);
    __syncthreads();
    for (int kt = 0; kt < KT; kt++) {
        int s = kt & 1;
        if (kt + 1 < KT) fetch(kt + 1);
        compute(s);
        if (kt + 1 < KT) sts(s ^ 1, kt + 1);
        __syncthreads();
    }

    // ---- epilogue ----
    if constexpr (MODE == 0 || MODE == 2) {
        float* dst = (MODE == 0) ? g_qkv : g_hid;
        constexpr int NN = (MODE == 0) ? QKVN : HIDDEN;
        #pragma unroll
        for (int mi = 0; mi < 4; mi++) {
            #pragma unroll
            for (int ni = 0; ni < 4; ni++) {
                int m = m0 + wr * 64 + mi * 16 + g;
                int n = n0 + wc * 32 + ni * 8 + 2 * c;
                float b0 = __ldg(&bias[n]), b1 = __ldg(&bias[n + 1]);
                #pragma unroll
                for (int half = 0; half < 2; half++) {
                    int mm = m + half * 8;
                    float v0 = acc[mi][ni][2 * half]     + b0;
                    float v1 = acc[mi][ni][2 * half + 1] + b1;
                    if constexpr (MODE == 2) {
                        v0 = 0.5f * v0 * (1.0f + erff(v0 * 0.70710678118654752f));
                        v1 = 0.5f * v1 * (1.0f + erff(v1 * 0.70710678118654752f));
                    }
                    *(float2*)(dst + (size_t)mm * NN + n) = make_float2(v0, v1);
                }
            }
        }
    } else if constexpr (MODE == 1) {
        // stage NCHW shortcut m-coalesced, add in frag pass, write row-major
        #pragma unroll 1
        for (int p = 0; p < 2; p++) {
            int ml = tid & 63;
            int m = m0 + p * 64 + ml;
            int bb = m / HWD, hw = m % HWD;
            const float* xb = x + (size_t)bb * CC * HWD + hw;
            #pragma unroll 4
            for (int it = 0; it < 32; it++) {
                int col = it * 4 + (tid >> 6);
                Cs[ml * 133 + col] = xb[(size_t)(n0 + col) * HWD];
            }
            __syncthreads();
            if (wr == p) {
                #pragma unroll
                for (int mi = 0; mi < 4; mi++) {
                    #pragma unroll
                    for (int ni = 0; ni < 4; ni++) {
                        int n  = n0 + wc * 32 + ni * 8 + 2 * c;
                        int cn = wc * 32 + ni * 8 + 2 * c;
                        float b0 = __ldg(&bias[n]), b1 = __ldg(&bias[n + 1]);
                        #pragma unroll
                        for (int half = 0; half < 2; half++) {
                            int r = mi * 16 + g + half * 8;
                            int m = m0 + p * 64 + r;
                            float v0 = acc[mi][ni][2 * half]     + b0 + Cs[r * 133 + cn];
                            float v1 = acc[mi][ni][2 * half + 1] + b1 + Cs[r * 133 + cn + 1];
                            *(float2*)(g_seq1 + (size_t)m * CC + n) = make_float2(v0, v1);
                        }
                    }
                }
            }
            __syncthreads();
        }
    } else {  // MODE 3: add g_seq2 (row-major read) in frag pass, write NCHW m-coalesced
        #pragma unroll 1
        for (int p = 0; p < 2; p++) {
            if (wr == p) {
                #pragma unroll
                for (int mi = 0; mi < 4; mi++) {
                    #pragma unroll
                    for (int ni = 0; ni < 4; ni++) {
                        int n  = n0 + wc * 32 + ni * 8 + 2 * c;
                        int cn = wc * 32 + ni * 8 + 2 * c;
                        float b0 = __ldg(&bias[n]), b1 = __ldg(&bias[n + 1]);
                        #pragma unroll
                        for (int half = 0; half < 2; half++) {
                            int r = mi * 16 + g + half * 8;
                            int m = m0 + p * 64 + r;
                            float2 s2 = *(const float2*)(g_seq2 + (size_t)m * CC + n);
                            Cs[r * 133 + cn]     = acc[mi][ni][2 * half]     + b0 + s2.x;
                            Cs[r * 133 + cn + 1] = acc[mi][ni][2 * half + 1] + b1 + s2.y;
                        }
                    }
                }
            }
            __syncthreads();
            int ml = tid & 63;
            int m = m0 + p * 64 + ml;
            int bb = m / HWD, hw = m % HWD;
            float* ob = out + (size_t)bb * CC * HWD + hw;
            #pragma unroll 4
            for (int it = 0; it < 32; it++) {
                int col = it * 4 + (tid >> 6);
                ob[(size_t)(n0 + col) * HWD] = Cs[ml * 133 + col];
            }
            __syncthreads();
        }
    }
}

// ---------------- windowed attention ----------------
__global__ __launch_bounds__(256) void attn_kernel(const float* __restrict__ bias_table) {
    int wh = blockIdx.x;
    int w  = wh / NHEADS;
    int h  = wh - w * NHEADS;
    int b  = w >> 6;
    int wr = w & 63;
    int nh = wr >> 3, nw = wr & 7;
    int tid = threadIdx.x;

    __shared__ float qs[49][33], ks[49][33], vs[49][33];
    __shared__ float ss[49][52];
    __shared__ int gtok[49];
    if (tid < 49) {
        int i = tid / 7, j = tid - i * 7;
        gtok[tid] = b * HWD + (nh * 7 + i) * SIDE + (nw * 7 + j);
    }
    __syncthreads();

    for (int idx = tid; idx < 49 * 32; idx += 256) {
        int n = idx >> 5, d = idx & 31;
        size_t base = (size_t)gtok[n] * QKVN + h * HEADD + d;
        qs[n][d] = g_qkv[base];
        ks[n][d] = g_qkv[base + 384];
        vs[n][d] = g_qkv[base + 768];
    }
    __syncthreads();

    for (int idx = tid; idx < 49 * 49; idx += 256) {
        int n = idx / 49, m = idx - n * 49;
        float a = 0.f;
        #pragma unroll
        for (int d = 0; d < 32; d++) a = fmaf(qs[n][d], ks[m][d], a);
        int i1 = n / 7, j1 = n - i1 * 7;
        int i2 = m / 7, j2 = m - i2 * 7;
        int ridx = (i1 - i2 + 6) * 13 + (j1 - j2 + 6);
        ss[n][m] = a * ATT_SCALE + __ldg(&bias_table[ridx * NHEADS + h]);
    }
    __syncthreads();

    int warp = tid >> 5, lane = tid & 31;
    for (int n = warp; n < 49; n += 8) {
        float e0 = ss[n][lane];
        float e1 = (lane + 32 < 49) ? ss[n][lane + 32] : -1e30f;
        float mx = fmaxf(e0, e1);
        #pragma unroll
        for (int o = 16; o; o >>= 1) mx = fmaxf(mx, __shfl_xor_sync(0xffffffffu, mx, o));
        float x0 = __expf(e0 - mx);
        float x1 = (lane + 32 < 49) ? __expf(e1 - mx) : 0.f;
        float sm = x0 + x1;
        #pragma unroll
        for (int o = 16; o; o >>= 1) sm += __shfl_xor_sync(0xffffffffu, sm, o);
        float inv = 1.0f / sm;
        ss[n][lane] = x0 * inv;
        if (lane + 32 < 49) ss[n][lane + 32] = x1 * inv;
    }
    __syncthreads();

    for (int idx = tid; idx < 49 * 32; idx += 256) {
        int n = idx >> 5, d = idx & 31;
        float a = 0.f;
        #pragma unroll
        for (int m = 0; m < 49; m++) a = fmaf(ss[n][m], vs[m][d], a);
        g_att[(size_t)gtok[n] * CC + h * HEADD + d] = a;
    }
}

// ---------------- depthwise 3x3 conv + BN ----------------
__global__ void conv_bn_kernel(const float* __restrict__ conv_w,
                               const float* __restrict__ bn_g,
                               const float* __restrict__ bn_b,
                               const float* __restrict__ bn_mean,
                               const float* __restrict__ bn_var) {
    int idx = blockIdx.x * 256 + threadIdx.x;
    if (idx >= TOKENS * CC) return;
    int c   = idx % CC;
    int tok = idx / CC;
    int b   = tok / HWD;
    int hw  = tok - b * HWD;
    int h   = hw / SIDE, w = hw - h * SIDE;
    float acc = 0.f;
    #pragma unroll
    for (int dy = 0; dy < 3; dy++) {
        int y = h + dy - 1;
        if (y < 0 || y >= SIDE) continue;
        #pragma unroll
        for (int dx = 0; dx < 3; dx++) {
            int xx = w + dx - 1;
            if (xx < 0 || xx >= SIDE) continue;
            acc = fmaf(g_seq1[(size_t)(b * HWD + y * SIDE + xx) * CC + c],
                       __ldg(&conv_w[c * 9 + dy * 3 + dx]), acc);
        }
    }
    float sc = __ldg(&bn_g[c]) * rsqrtf(__ldg(&bn_var[c]) + LN_EPS);
    g_seq2[idx] = (acc - __ldg(&bn_mean[c])) * sc + __ldg(&bn_b[c]);
}

// ---------------------------------------------------------------------------
extern "C" void kernel_launch(void* const* d_in, const int* in_sizes, int n_in,
                              void* d_out, int out_size) {
    const float* x          = (const float*)d_in[0];
    const float* ln_g       = (const float*)d_in[1];
    const float* ln_b       = (const float*)d_in[2];
    const float* qkv_w      = (const float*)d_in[3];
    const float* qkv_b      = (const float*)d_in[4];
    const float* proj_w     = (const float*)d_in[5];
    const float* proj_b     = (const float*)d_in[6];
    const float* bias_table = (const float*)d_in[7];
    const float* conv_w     = (const float*)d_in[8];
    const float* bn_g       = (const float*)d_in[9];
    const float* bn_b       = (const float*)d_in[10];
    const float* bn_mean    = (const float*)d_in[11];
    const float* bn_var     = (const float*)d_in[12];
    const float* w1         = (const float*)d_in[13];
    const float* b1         = (const float*)d_in[14];
    const float* w2         = (const float*)d_in[15];
    const float* b2         = (const float*)d_in[16];
    float* out = (float*)d_out;

    ln_stats_kernel<<<TOKENS / 64, 256>>>(x);
    mma_gemm<0><<<dim3(QKVN / 128, TOKENS / 128), 256>>>(x, qkv_w, qkv_b, ln_g, ln_b, nullptr);
    attn_kernel<<<NWIN * NHEADS, 256>>>(bias_table);
    mma_gemm<1><<<dim3(CC / 128, TOKENS / 128), 256>>>(x, proj_w, proj_b, nullptr, nullptr, nullptr);
    conv_bn_kernel<<<(TOKENS * CC + 255) / 256, 256>>>(conv_w, bn_g, bn_b, bn_mean, bn_var);
    mma_gemm<2><<<dim3(HIDDEN / 128, TOKENS / 128), 256>>>(nullptr, w1, b1, nullptr, nullptr, nullptr);
    mma_gemm<3><<<dim3(CC / 128, TOKENS / 128), 256>>>(nullptr, w2, b2, nullptr, nullptr, out);
}

// round 4
// speedup vs baseline: 2.2321x; 1.1230x over previous
#include <cuda_runtime.h>
#include <math.h>
#include <stdint.h>

#define CC      384
#define SIDE    56
#define HWD     3136
#define TOKENS  100352
#define NHEADS  12
#define HEADD   32
#define NWIN    2048
#define HIDDEN  1536
#define QKVN    1152
#define LN_EPS  1e-5f
#define ATT_SCALE 0.17677669529663687f

// ---------------- scratch ----------------
__device__ float g_mean[TOKENS];
__device__ float g_rstd[TOKENS];
__device__ float g_qkv[(size_t)TOKENS * QKVN];
__device__ float g_att[(size_t)TOKENS * CC];
__device__ float g_seq1[(size_t)TOKENS * CC];
__device__ float g_seq2[(size_t)TOKENS * CC];
__device__ float g_hid[(size_t)TOKENS * HIDDEN];

__device__ __forceinline__ void mma_tf32(float* d, const uint32_t* a, const uint32_t* b) {
    asm volatile(
        "mma.sync.aligned.m16n8k8.row.col.f32.tf32.tf32.f32 "
        "{%0,%1,%2,%3},{%4,%5,%6,%7},{%8,%9},{%0,%1,%2,%3};"
        : "+f"(d[0]), "+f"(d[1]), "+f"(d[2]), "+f"(d[3])
        : "r"(a[0]), "r"(a[1]), "r"(a[2]), "r"(a[3]), "r"(b[0]), "r"(b[1]));
}

#define CPA16(sa, gp) asm volatile("cp.async.cg.shared.global [%0], [%1], 16;" :: "r"(sa), "l"(gp))
#define CPA_COMMIT()  asm volatile("cp.async.commit_group;")
#define CPA_WAIT0()   asm volatile("cp.async.wait_group 0;")

// ---------------- LayerNorm statistics --------------
__global__ void ln_stats_kernel(const float* __restrict__ x) {
    int blk = blockIdx.x;
    int b   = blk / (HWD / 64);
    int hw0 = (blk % (HWD / 64)) * 64;
    int t   = threadIdx.x & 63;
    int cg  = threadIdx.x >> 6;
    const float* xp = x + (size_t)b * CC * HWD + hw0 + t;
    float s = 0.f, ss = 0.f;
    for (int c = cg; c < CC; c += 4) {
        float v = xp[(size_t)c * HWD];
        s += v; ss += v * v;
    }
    __shared__ float sh[2][4][64];
    sh[0][cg][t] = s; sh[1][cg][t] = ss;
    __syncthreads();
    if (cg == 0) {
        float S  = sh[0][0][t] + sh[0][1][t] + sh[0][2][t] + sh[0][3][t];
        float SS = sh[1][0][t] + sh[1][1][t] + sh[1][2][t] + sh[1][3][t];
        float mu  = S * (1.0f / CC);
        float var = SS * (1.0f / CC) - mu * mu;
        int g = b * HWD + hw0 + t;
        g_mean[g] = mu;
        g_rstd[g] = rsqrtf(var + LN_EPS);
    }
}

// ---------------- tf32 tensor-core GEMM (cp.async, conflict-free smem) -----
// smem layout: A buf s at sm[s*2560], row-major [128 rows][16 k + 4 pad]
//              B buf s at sm[5120 + s*2560], same layout ([n][k])
// MODE 0: A = LayerNorm(x) (NCHW) -> g_qkv
// MODE 1: A = g_att, += shortcut x (NCHW) -> g_seq1
// MODE 2: A = g_seq2, GELU -> g_hid
// MODE 3: A = g_hid, += g_seq2 -> out (NCHW)
template<int MODE>
__global__ __launch_bounds__(256) void mma_gemm(
    const float* __restrict__ x,
    const float* __restrict__ Wt,     // [N][K] row-major
    const float* __restrict__ bias,
    const float* __restrict__ lng,
    const float* __restrict__ lnb,
    float* __restrict__ out)
{
    constexpr int K  = (MODE == 3) ? HIDDEN : CC;
    constexpr int KT = K / 16;
    const int m0  = blockIdx.y * 128;
    const int n0  = blockIdx.x * 128;
    const int tid = threadIdx.x;
    const int lane = tid & 31, warp = tid >> 5;
    const int wr = warp >> 2, wc = warp & 3;      // 64x32 warp tile
    const int g  = lane >> 2, c = lane & 3;

    __shared__ uint32_t sm[10240];                // 40 KB
    const uint32_t smem_base = (uint32_t)__cvta_generic_to_shared(sm);
    float* Cs = (float*)sm;                       // epilogue staging [64][133]

    float acc[4][4][4];
    #pragma unroll
    for (int i = 0; i < 4; i++)
        #pragma unroll
        for (int j = 0; j < 4; j++)
            #pragma unroll
            for (int q = 0; q < 4; q++) acc[i][j][q] = 0.f;

    // ---- A source ----
    const float* Arow = nullptr;
    if constexpr (MODE == 1) Arow = g_att;
    if constexpr (MODE == 2) Arow = g_seq2;
    if constexpr (MODE == 3) Arow = g_hid;

    const int lr  = tid & 127;   // MODE0 row
    const int lkp = tid >> 7;    // MODE0 k phase
    const float* xr = nullptr;
    float mu = 0.f, rsd = 0.f;
    if constexpr (MODE == 0) {
        int gm = m0 + lr;
        int bb = gm / HWD, hw = gm % HWD;
        xr = x + (size_t)bb * CC * HWD + hw;
        mu = g_mean[gm]; rsd = g_rstd[gm];
    }

    const int seg_row = tid >> 1;                 // cp.async map: 2 segs/thread
    const int seg_kq0 = (tid & 1) * 2;            // kq in {0,1} then {2,3}

    float fA[8];                                  // MODE0 staged LN inputs

    auto cpasync_load = [&](int kt, int s) {
        int k0 = kt * 16;
        #pragma unroll
        for (int j = 0; j < 2; j++) {
            int kq = seg_kq0 + j;
            if constexpr (MODE != 0) {
                CPA16(smem_base + (uint32_t)(s * 2560 + seg_row * 20 + kq * 4) * 4,
                      Arow + (size_t)(m0 + seg_row) * K + k0 + kq * 4);
            }
            CPA16(smem_base + (uint32_t)(5120 + s * 2560 + seg_row * 20 + kq * 4) * 4,
                  Wt + (size_t)(n0 + seg_row) * K + k0 + kq * 4);
        }
        CPA_COMMIT();
    };
    auto fetchA0 = [&](int kt) {
        int k0 = kt * 16;
        #pragma unroll
        for (int i = 0; i < 8; i++)
            fA[i] = xr[(size_t)(k0 + lkp + 2 * i) * HWD];
    };
    auto stsA0 = [&](int s, int kt) {
        uint32_t* A = sm + s * 2560;
        int k0 = kt * 16;
        #pragma unroll
        for (int i = 0; i < 8; i++) {
            int kk = lkp + 2 * i;
            int k = k0 + kk;
            A[lr * 20 + kk] =
                __float_as_uint((fA[i] - mu) * rsd * __ldg(&lng[k]) + __ldg(&lnb[k]));
        }
    };
    auto compute = [&](int s) {
        const uint32_t* A = sm + s * 2560;
        const uint32_t* B = sm + 5120 + s * 2560;
        #pragma unroll
        for (int h = 0; h < 2; h++) {
            int kk = h * 8;
            uint32_t af[4][4], bf[4][2];
            #pragma unroll
            for (int mi = 0; mi < 4; mi++) {
                int mrow = wr * 64 + mi * 16 + g;
                af[mi][0] = A[mrow * 20 + kk + c];
                af[mi][1] = A[(mrow + 8) * 20 + kk + c];
                af[mi][2] = A[mrow * 20 + kk + c + 4];
                af[mi][3] = A[(mrow + 8) * 20 + kk + c + 4];
            }
            #pragma unroll
            for (int ni = 0; ni < 4; ni++) {
                int ncol = wc * 32 + ni * 8 + g;
                bf[ni][0] = B[ncol * 20 + kk + c];
                bf[ni][1] = B[ncol * 20 + kk + c + 4];
            }
            #pragma unroll
            for (int mi = 0; mi < 4; mi++)
                #pragma unroll
                for (int ni = 0; ni < 4; ni++)
                    mma_tf32(acc[mi][ni], af[mi], bf[ni]);
        }
    };

    // ---- mainloop ----
    if constexpr (MODE == 0) { fetchA0(0); }
    cpasync_load(0, 0);
    if constexpr (MODE == 0) { stsA0(0, 0); }
    CPA_WAIT0();
    __syncthreads();
    for (int kt = 0; kt < KT; kt++) {
        int s = kt & 1;
        bool next = (kt + 1 < KT);
        if (next) {
            cpasync_load(kt + 1, s ^ 1);
            if constexpr (MODE == 0) fetchA0(kt + 1);
        }
        compute(s);
        if constexpr (MODE == 0) { if (next) stsA0(s ^ 1, kt + 1); }
        if (next) CPA_WAIT0();
        __syncthreads();
    }

    // ---- epilogue ----
    if constexpr (MODE == 0 || MODE == 2) {
        float* dst = (MODE == 0) ? g_qkv : g_hid;
        constexpr int NN = (MODE == 0) ? QKVN : HIDDEN;
        #pragma unroll
        for (int mi = 0; mi < 4; mi++) {
            #pragma unroll
            for (int ni = 0; ni < 4; ni++) {
                int m = m0 + wr * 64 + mi * 16 + g;
                int n = n0 + wc * 32 + ni * 8 + 2 * c;
                float b0 = __ldg(&bias[n]), b1 = __ldg(&bias[n + 1]);
                #pragma unroll
                for (int half = 0; half < 2; half++) {
                    int mm = m + half * 8;
                    float v0 = acc[mi][ni][2 * half]     + b0;
                    float v1 = acc[mi][ni][2 * half + 1] + b1;
                    if constexpr (MODE == 2) {
                        v0 = 0.5f * v0 * (1.0f + erff(v0 * 0.70710678118654752f));
                        v1 = 0.5f * v1 * (1.0f + erff(v1 * 0.70710678118654752f));
                    }
                    *(float2*)(dst + (size_t)mm * NN + n) = make_float2(v0, v1);
                }
            }
        }
    } else if constexpr (MODE == 1) {
        #pragma unroll 1
        for (int p = 0; p < 2; p++) {
            int ml = tid & 63;
            int m = m0 + p * 64 + ml;
            int bb = m / HWD, hw = m % HWD;
            const float* xb = x + (size_t)bb * CC * HWD + hw;
            #pragma unroll 4
            for (int it = 0; it < 32; it++) {
                int col = it * 4 + (tid >> 6);
                Cs[ml * 133 + col] = xb[(size_t)(n0 + col) * HWD];
            }
            __syncthreads();
            if (wr == p) {
                #pragma unroll
                for (int mi = 0; mi < 4; mi++) {
                    #pragma unroll
                    for (int ni = 0; ni < 4; ni++) {
                        int n  = n0 + wc * 32 + ni * 8 + 2 * c;
                        int cn = wc * 32 + ni * 8 + 2 * c;
                        float b0 = __ldg(&bias[n]), b1 = __ldg(&bias[n + 1]);
                        #pragma unroll
                        for (int half = 0; half < 2; half++) {
                            int r = mi * 16 + g + half * 8;
                            int m = m0 + p * 64 + r;
                            float v0 = acc[mi][ni][2 * half]     + b0 + Cs[r * 133 + cn];
                            float v1 = acc[mi][ni][2 * half + 1] + b1 + Cs[r * 133 + cn + 1];
                            *(float2*)(g_seq1 + (size_t)m * CC + n) = make_float2(v0, v1);
                        }
                    }
                }
            }
            __syncthreads();
        }
    } else {  // MODE 3
        #pragma unroll 1
        for (int p = 0; p < 2; p++) {
            if (wr == p) {
                #pragma unroll
                for (int mi = 0; mi < 4; mi++) {
                    #pragma unroll
                    for (int ni = 0; ni < 4; ni++) {
                        int n  = n0 + wc * 32 + ni * 8 + 2 * c;
                        int cn = wc * 32 + ni * 8 + 2 * c;
                        float b0 = __ldg(&bias[n]), b1 = __ldg(&bias[n + 1]);
                        #pragma unroll
                        for (int half = 0; half < 2; half++) {
                            int r = mi * 16 + g + half * 8;
                            int m = m0 + p * 64 + r;
                            float2 s2 = *(const float2*)(g_seq2 + (size_t)m * CC + n);
                            Cs[r * 133 + cn]     = acc[mi][ni][2 * half]     + b0 + s2.x;
                            Cs[r * 133 + cn + 1] = acc[mi][ni][2 * half + 1] + b1 + s2.y;
                        }
                    }
                }
            }
            __syncthreads();
            int ml = tid & 63;
            int m = m0 + p * 64 + ml;
            int bb = m / HWD, hw = m % HWD;
            float* ob = out + (size_t)bb * CC * HWD + hw;
            #pragma unroll 4
            for (int it = 0; it < 32; it++) {
                int col = it * 4 + (tid >> 6);
                ob[(size_t)(n0 + col) * HWD] = Cs[ml * 133 + col];
            }
            __syncthreads();
        }
    }
}

// ---------------- windowed attention ----------------
__global__ __launch_bounds__(256) void attn_kernel(const float* __restrict__ bias_table) {
    int wh = blockIdx.x;
    int w  = wh / NHEADS;
    int h  = wh - w * NHEADS;
    int b  = w >> 6;
    int wr = w & 63;
    int nh = wr >> 3, nw = wr & 7;
    int tid = threadIdx.x;

    __shared__ float qs[49][33], ks[49][33], vs[49][33];
    __shared__ float ss[49][52];
    __shared__ int gtok[49];
    if (tid < 49) {
        int i = tid / 7, j = tid - i * 7;
        gtok[tid] = b * HWD + (nh * 7 + i) * SIDE + (nw * 7 + j);
    }
    __syncthreads();

    for (int idx = tid; idx < 49 * 32; idx += 256) {
        int n = idx >> 5, d = idx & 31;
        size_t base = (size_t)gtok[n] * QKVN + h * HEADD + d;
        qs[n][d] = g_qkv[base];
        ks[n][d] = g_qkv[base + 384];
        vs[n][d] = g_qkv[base + 768];
    }
    __syncthreads();

    for (int idx = tid; idx < 49 * 49; idx += 256) {
        int n = idx / 49, m = idx - n * 49;
        float a = 0.f;
        #pragma unroll
        for (int d = 0; d < 32; d++) a = fmaf(qs[n][d], ks[m][d], a);
        int i1 = n / 7, j1 = n - i1 * 7;
        int i2 = m / 7, j2 = m - i2 * 7;
        int ridx = (i1 - i2 + 6) * 13 + (j1 - j2 + 6);
        ss[n][m] = a * ATT_SCALE + __ldg(&bias_table[ridx * NHEADS + h]);
    }
    __syncthreads();

    int warp = tid >> 5, lane = tid & 31;
    for (int n = warp; n < 49; n += 8) {
        float e0 = ss[n][lane];
        float e1 = (lane + 32 < 49) ? ss[n][lane + 32] : -1e30f;
        float mx = fmaxf(e0, e1);
        #pragma unroll
        for (int o = 16; o; o >>= 1) mx = fmaxf(mx, __shfl_xor_sync(0xffffffffu, mx, o));
        float x0 = __expf(e0 - mx);
        float x1 = (lane + 32 < 49) ? __expf(e1 - mx) : 0.f;
        float sm = x0 + x1;
        #pragma unroll
        for (int o = 16; o; o >>= 1) sm += __shfl_xor_sync(0xffffffffu, sm, o);
        float inv = 1.0f / sm;
        ss[n][lane] = x0 * inv;
        if (lane + 32 < 49) ss[n][lane + 32] = x1 * inv;
    }
    __syncthreads();

    for (int idx = tid; idx < 49 * 32; idx += 256) {
        int n = idx >> 5, d = idx & 31;
        float a = 0.f;
        #pragma unroll
        for (int m = 0; m < 49; m++) a = fmaf(ss[n][m], vs[m][d], a);
        g_att[(size_t)gtok[n] * CC + h * HEADD + d] = a;
    }
}

// ---------------- depthwise 3x3 conv + BN ----------------
__global__ void conv_bn_kernel(const float* __restrict__ conv_w,
                               const float* __restrict__ bn_g,
                               const float* __restrict__ bn_b,
                               const float* __restrict__ bn_mean,
                               const float* __restrict__ bn_var) {
    int idx = blockIdx.x * 256 + threadIdx.x;
    if (idx >= TOKENS * CC) return;
    int c   = idx % CC;
    int tok = idx / CC;
    int b   = tok / HWD;
    int hw  = tok - b * HWD;
    int h   = hw / SIDE, w = hw - h * SIDE;
    float acc = 0.f;
    #pragma unroll
    for (int dy = 0; dy < 3; dy++) {
        int y = h + dy - 1;
        if (y < 0 || y >= SIDE) continue;
        #pragma unroll
        for (int dx = 0; dx < 3; dx++) {
            int xx = w + dx - 1;
            if (xx < 0 || xx >= SIDE) continue;
            acc = fmaf(g_seq1[(size_t)(b * HWD + y * SIDE + xx) * CC + c],
                       __ldg(&conv_w[c * 9 + dy * 3 + dx]), acc);
        }
    }
    float sc = __ldg(&bn_g[c]) * rsqrtf(__ldg(&bn_var[c]) + LN_EPS);
    g_seq2[idx] = (acc - __ldg(&bn_mean[c])) * sc + __ldg(&bn_b[c]);
}

// ---------------------------------------------------------------------------
extern "C" void kernel_launch(void* const* d_in, const int* in_sizes, int n_in,
                              void* d_out, int out_size) {
    const float* x          = (const float*)d_in[0];
    const float* ln_g       = (const float*)d_in[1];
    const float* ln_b       = (const float*)d_in[2];
    const float* qkv_w      = (const float*)d_in[3];
    const float* qkv_b      = (const float*)d_in[4];
    const float* proj_w     = (const float*)d_in[5];
    const float* proj_b     = (const float*)d_in[6];
    const float* bias_table = (const float*)d_in[7];
    const float* conv_w     = (const float*)d_in[8];
    const float* bn_g       = (const float*)d_in[9];
    const float* bn_b       = (const float*)d_in[10];
    const float* bn_mean    = (const float*)d_in[11];
    const float* bn_var     = (const float*)d_in[12];
    const float* w1         = (const float*)d_in[13];
    const float* b1         = (const float*)d_in[14];
    const float* w2         = (const float*)d_in[15];
    const float* b2         = (const float*)d_in[16];
    float* out = (float*)d_out;

    ln_stats_kernel<<<TOKENS / 64, 256>>>(x);
    mma_gemm<0><<<dim3(QKVN / 128, TOKENS / 128), 256>>>(x, qkv_w, qkv_b, ln_g, ln_b, nullptr);
    attn_kernel<<<NWIN * NHEADS, 256>>>(bias_table);
    mma_gemm<1><<<dim3(CC / 128, TOKENS / 128), 256>>>(x, proj_w, proj_b, nullptr, nullptr, nullptr);
    conv_bn_kernel<<<(TOKENS * CC + 255) / 256, 256>>>(conv_w, bn_g, bn_b, bn_mean, bn_var);
    mma_gemm<2><<<dim3(HIDDEN / 128, TOKENS / 128), 256>>>(nullptr, w1, b1, nullptr, nullptr, nullptr);
    mma_gemm<3><<<dim3(CC / 128, TOKENS / 128), 256>>>(nullptr, w2, b2, nullptr, nullptr, out);
}

// round 5
// speedup vs baseline: 2.2347x; 1.0012x over previous
#include <cuda_runtime.h>
#include <math.h>
#include <stdint.h>

#define CC      384
#define SIDE    56
#define HWD     3136
#define TOKENS  100352
#define NHEADS  12
#define HEADD   32
#define NWIN    2048
#define HIDDEN  1536
#define QKVN    1152
#define LN_EPS  1e-5f
#define ATT_SCALE 0.17677669529663687f

#define STAGES  4
#define SMEM_BYTES (STAGES * 2 * 2560 * 4)   // 81920

// ---------------- scratch ----------------
__device__ float g_mean[TOKENS];
__device__ float g_rstd[TOKENS];
__device__ float g_qkv[(size_t)TOKENS * QKVN];
__device__ float g_att[(size_t)TOKENS * CC];
__device__ float g_seq1[(size_t)TOKENS * CC];
__device__ float g_seq2[(size_t)TOKENS * CC];
__device__ float g_hid[(size_t)TOKENS * HIDDEN];

__device__ __forceinline__ void mma_tf32(float* d, const uint32_t* a, const uint32_t* b) {
    asm volatile(
        "mma.sync.aligned.m16n8k8.row.col.f32.tf32.tf32.f32 "
        "{%0,%1,%2,%3},{%4,%5,%6,%7},{%8,%9},{%0,%1,%2,%3};"
        : "+f"(d[0]), "+f"(d[1]), "+f"(d[2]), "+f"(d[3])
        : "r"(a[0]), "r"(a[1]), "r"(a[2]), "r"(a[3]), "r"(b[0]), "r"(b[1]));
}

#define CPA16(sa, gp)  asm volatile("cp.async.cg.shared.global [%0], [%1], 16;" :: "r"(sa), "l"(gp))
#define CPA_COMMIT()   asm volatile("cp.async.commit_group;")
#define CPA_WAIT(n)    asm volatile("cp.async.wait_group %0;" :: "n"(n))

// ---------------- LayerNorm statistics --------------
__global__ void ln_stats_kernel(const float* __restrict__ x) {
    int blk = blockIdx.x;
    int b   = blk / (HWD / 64);
    int hw0 = (blk % (HWD / 64)) * 64;
    int t   = threadIdx.x & 63;
    int cg  = threadIdx.x >> 6;
    const float* xp = x + (size_t)b * CC * HWD + hw0 + t;
    float s = 0.f, ss = 0.f;
    for (int c = cg; c < CC; c += 4) {
        float v = xp[(size_t)c * HWD];
        s += v; ss += v * v;
    }
    __shared__ float sh[2][4][64];
    sh[0][cg][t] = s; sh[1][cg][t] = ss;
    __syncthreads();
    if (cg == 0) {
        float S  = sh[0][0][t] + sh[0][1][t] + sh[0][2][t] + sh[0][3][t];
        float SS = sh[1][0][t] + sh[1][1][t] + sh[1][2][t] + sh[1][3][t];
        float mu  = S * (1.0f / CC);
        float var = SS * (1.0f / CC) - mu * mu;
        int g = b * HWD + hw0 + t;
        g_mean[g] = mu;
        g_rstd[g] = rsqrtf(var + LN_EPS);
    }
}

// ---------------- tf32 tensor-core GEMM (4-stage cp.async pipeline) --------
// dyn smem: A stage s at sm[s*2560] ([128 rows][16k + 4 pad]);
//           B stage s at sm[10240 + s*2560]
template<int MODE>
__global__ __launch_bounds__(256) void mma_gemm(
    const float* __restrict__ x,
    const float* __restrict__ Wt,     // [N][K] row-major
    const float* __restrict__ bias,
    const float* __restrict__ lng,
    const float* __restrict__ lnb,
    float* __restrict__ out)
{
    constexpr int K  = (MODE == 3) ? HIDDEN : CC;
    constexpr int KT = K / 16;
    const int m0  = blockIdx.y * 128;
    const int n0  = blockIdx.x * 128;
    const int tid = threadIdx.x;
    const int lane = tid & 31, warp = tid >> 5;
    const int wr = warp >> 2, wc = warp & 3;      // 64x32 warp tile
    const int g  = lane >> 2, c = lane & 3;

    extern __shared__ uint32_t sm[];
    const uint32_t smem_base = (uint32_t)__cvta_generic_to_shared(sm);
    float* Cs = (float*)sm;                       // epilogue staging [64][133]

    float acc[4][4][4];
    #pragma unroll
    for (int i = 0; i < 4; i++)
        #pragma unroll
        for (int j = 0; j < 4; j++)
            #pragma unroll
            for (int q = 0; q < 4; q++) acc[i][j][q] = 0.f;

    // ---- A source ----
    const float* Arow = nullptr;
    if constexpr (MODE == 1) Arow = g_att;
    if constexpr (MODE == 2) Arow = g_seq2;
    if constexpr (MODE == 3) Arow = g_hid;

    const int lr  = tid & 127;   // MODE0 row
    const int lkp = tid >> 7;    // MODE0 k phase
    const float* xr = nullptr;
    float mu = 0.f, rsd = 0.f;
    if constexpr (MODE == 0) {
        int gm = m0 + lr;
        int bb = gm / HWD, hw = gm % HWD;
        xr = x + (size_t)bb * CC * HWD + hw;
        mu = g_mean[gm]; rsd = g_rstd[gm];
    }

    const int seg_row = tid >> 1;
    const int seg_kq0 = (tid & 1) * 2;

    float fA[8];                                  // MODE0 staged LN inputs

    auto cpasync_load = [&](int kt) {
        int s = kt & (STAGES - 1);
        int k0 = kt * 16;
        #pragma unroll
        for (int j = 0; j < 2; j++) {
            int kq = seg_kq0 + j;
            if constexpr (MODE != 0) {
                CPA16(smem_base + (uint32_t)(s * 2560 + seg_row * 20 + kq * 4) * 4,
                      Arow + (size_t)(m0 + seg_row) * K + k0 + kq * 4);
            }
            CPA16(smem_base + (uint32_t)(10240 + s * 2560 + seg_row * 20 + kq * 4) * 4,
                  Wt + (size_t)(n0 + seg_row) * K + k0 + kq * 4);
        }
        CPA_COMMIT();
    };
    auto fetchA0 = [&](int kt) {
        int k0 = kt * 16;
        #pragma unroll
        for (int i = 0; i < 8; i++)
            fA[i] = xr[(size_t)(k0 + lkp + 2 * i) * HWD];
    };
    auto stsA0 = [&](int kt) {
        uint32_t* A = sm + (kt & (STAGES - 1)) * 2560;
        int k0 = kt * 16;
        #pragma unroll
        for (int i = 0; i < 8; i++) {
            int kk = lkp + 2 * i;
            int k = k0 + kk;
            A[lr * 20 + kk] =
                __float_as_uint((fA[i] - mu) * rsd * __ldg(&lng[k]) + __ldg(&lnb[k]));
        }
    };
    auto compute = [&](int kt) {
        const uint32_t* A = sm + (kt & (STAGES - 1)) * 2560;
        const uint32_t* B = sm + 10240 + (kt & (STAGES - 1)) * 2560;
        #pragma unroll
        for (int h = 0; h < 2; h++) {
            int kk = h * 8;
            uint32_t af[4][4], bf[4][2];
            #pragma unroll
            for (int mi = 0; mi < 4; mi++) {
                int mrow = wr * 64 + mi * 16 + g;
                af[mi][0] = A[mrow * 20 + kk + c];
                af[mi][1] = A[(mrow + 8) * 20 + kk + c];
                af[mi][2] = A[mrow * 20 + kk + c + 4];
                af[mi][3] = A[(mrow + 8) * 20 + kk + c + 4];
            }
            #pragma unroll
            for (int ni = 0; ni < 4; ni++) {
                int ncol = wc * 32 + ni * 8 + g;
                bf[ni][0] = B[ncol * 20 + kk + c];
                bf[ni][1] = B[ncol * 20 + kk + c + 4];
            }
            #pragma unroll
            for (int mi = 0; mi < 4; mi++)
                #pragma unroll
                for (int ni = 0; ni < 4; ni++)
                    mma_tf32(acc[mi][ni], af[mi], bf[ni]);
        }
    };

    // ---- prologue: fill 3 stages ----
    if constexpr (MODE == 0) {
        fetchA0(0); stsA0(0);          // tile0 A straight to smem
        fetchA0(1);                    // tile1 A staged in regs
    }
    cpasync_load(0);
    cpasync_load(1);
    cpasync_load(2);

    // ---- mainloop ----
    for (int kt = 0; kt < KT; kt++) {
        CPA_WAIT(2);                   // tile kt landed (issued 3 iters ago)
        __syncthreads();
        if constexpr (MODE == 0) {
            if (kt + 1 < KT) stsA0(kt + 1);
        }
        if (kt + 3 < KT) cpasync_load(kt + 3);
        if constexpr (MODE == 0) {
            if (kt + 2 < KT) fetchA0(kt + 2);
        }
        compute(kt);
    }
    __syncthreads();

    // ---- epilogue ----
    if constexpr (MODE == 0 || MODE == 2) {
        float* dst = (MODE == 0) ? g_qkv : g_hid;
        constexpr int NN = (MODE == 0) ? QKVN : HIDDEN;
        #pragma unroll
        for (int mi = 0; mi < 4; mi++) {
            #pragma unroll
            for (int ni = 0; ni < 4; ni++) {
                int m = m0 + wr * 64 + mi * 16 + g;
                int n = n0 + wc * 32 + ni * 8 + 2 * c;
                float b0 = __ldg(&bias[n]), b1 = __ldg(&bias[n + 1]);
                #pragma unroll
                for (int half = 0; half < 2; half++) {
                    int mm = m + half * 8;
                    float v0 = acc[mi][ni][2 * half]     + b0;
                    float v1 = acc[mi][ni][2 * half + 1] + b1;
                    if constexpr (MODE == 2) {
                        v0 = 0.5f * v0 * (1.0f + erff(v0 * 0.70710678118654752f));
                        v1 = 0.5f * v1 * (1.0f + erff(v1 * 0.70710678118654752f));
                    }
                    *(float2*)(dst + (size_t)mm * NN + n) = make_float2(v0, v1);
                }
            }
        }
    } else if constexpr (MODE == 1) {
        #pragma unroll 1
        for (int p = 0; p < 2; p++) {
            int ml = tid & 63;
            int m = m0 + p * 64 + ml;
            int bb = m / HWD, hw = m % HWD;
            const float* xb = x + (size_t)bb * CC * HWD + hw;
            #pragma unroll 4
            for (int it = 0; it < 32; it++) {
                int col = it * 4 + (tid >> 6);
                Cs[ml * 133 + col] = xb[(size_t)(n0 + col) * HWD];
            }
            __syncthreads();
            if (wr == p) {
                #pragma unroll
                for (int mi = 0; mi < 4; mi++) {
                    #pragma unroll
                    for (int ni = 0; ni < 4; ni++) {
                        int n  = n0 + wc * 32 + ni * 8 + 2 * c;
                        int cn = wc * 32 + ni * 8 + 2 * c;
                        float b0 = __ldg(&bias[n]), b1 = __ldg(&bias[n + 1]);
                        #pragma unroll
                        for (int half = 0; half < 2; half++) {
                            int r = mi * 16 + g + half * 8;
                            int m = m0 + p * 64 + r;
                            float v0 = acc[mi][ni][2 * half]     + b0 + Cs[r * 133 + cn];
                            float v1 = acc[mi][ni][2 * half + 1] + b1 + Cs[r * 133 + cn + 1];
                            *(float2*)(g_seq1 + (size_t)m * CC + n) = make_float2(v0, v1);
                        }
                    }
                }
            }
            __syncthreads();
        }
    } else {  // MODE 3
        #pragma unroll 1
        for (int p = 0; p < 2; p++) {
            if (wr == p) {
                #pragma unroll
                for (int mi = 0; mi < 4; mi++) {
                    #pragma unroll
                    for (int ni = 0; ni < 4; ni++) {
                        int n  = n0 + wc * 32 + ni * 8 + 2 * c;
                        int cn = wc * 32 + ni * 8 + 2 * c;
                        float b0 = __ldg(&bias[n]), b1 = __ldg(&bias[n + 1]);
                        #pragma unroll
                        for (int half = 0; half < 2; half++) {
                            int r = mi * 16 + g + half * 8;
                            int m = m0 + p * 64 + r;
                            float2 s2 = *(const float2*)(g_seq2 + (size_t)m * CC + n);
                            Cs[r * 133 + cn]     = acc[mi][ni][2 * half]     + b0 + s2.x;
                            Cs[r * 133 + cn + 1] = acc[mi][ni][2 * half + 1] + b1 + s2.y;
                        }
                    }
                }
            }
            __syncthreads();
            int ml = tid & 63;
            int m = m0 + p * 64 + ml;
            int bb = m / HWD, hw = m % HWD;
            float* ob = out + (size_t)bb * CC * HWD + hw;
            #pragma unroll 4
            for (int it = 0; it < 32; it++) {
                int col = it * 4 + (tid >> 6);
                ob[(size_t)(n0 + col) * HWD] = Cs[ml * 133 + col];
            }
            __syncthreads();
        }
    }
}

// ---------------- windowed attention ----------------
__global__ __launch_bounds__(256) void attn_kernel(const float* __restrict__ bias_table) {
    int wh = blockIdx.x;
    int w  = wh / NHEADS;
    int h  = wh - w * NHEADS;
    int b  = w >> 6;
    int wr = w & 63;
    int nh = wr >> 3, nw = wr & 7;
    int tid = threadIdx.x;

    __shared__ float qs[49][33], ks[49][33], vs[49][33];
    __shared__ float ss[49][52];
    __shared__ int gtok[49];
    if (tid < 49) {
        int i = tid / 7, j = tid - i * 7;
        gtok[tid] = b * HWD + (nh * 7 + i) * SIDE + (nw * 7 + j);
    }
    __syncthreads();

    for (int idx = tid; idx < 49 * 32; idx += 256) {
        int n = idx >> 5, d = idx & 31;
        size_t base = (size_t)gtok[n] * QKVN + h * HEADD + d;
        qs[n][d] = g_qkv[base];
        ks[n][d] = g_qkv[base + 384];
        vs[n][d] = g_qkv[base + 768];
    }
    __syncthreads();

    for (int idx = tid; idx < 49 * 49; idx += 256) {
        int n = idx / 49, m = idx - n * 49;
        float a = 0.f;
        #pragma unroll
        for (int d = 0; d < 32; d++) a = fmaf(qs[n][d], ks[m][d], a);
        int i1 = n / 7, j1 = n - i1 * 7;
        int i2 = m / 7, j2 = m - i2 * 7;
        int ridx = (i1 - i2 + 6) * 13 + (j1 - j2 + 6);
        ss[n][m] = a * ATT_SCALE + __ldg(&bias_table[ridx * NHEADS + h]);
    }
    __syncthreads();

    int warp = tid >> 5, lane = tid & 31;
    for (int n = warp; n < 49; n += 8) {
        float e0 = ss[n][lane];
        float e1 = (lane + 32 < 49) ? ss[n][lane + 32] : -1e30f;
        float mx = fmaxf(e0, e1);
        #pragma unroll
        for (int o = 16; o; o >>= 1) mx = fmaxf(mx, __shfl_xor_sync(0xffffffffu, mx, o));
        float x0 = __expf(e0 - mx);
        float x1 = (lane + 32 < 49) ? __expf(e1 - mx) : 0.f;
        float sm = x0 + x1;
        #pragma unroll
        for (int o = 16; o; o >>= 1) sm += __shfl_xor_sync(0xffffffffu, sm, o);
        float inv = 1.0f / sm;
        ss[n][lane] = x0 * inv;
        if (lane + 32 < 49) ss[n][lane + 32] = x1 * inv;
    }
    __syncthreads();

    for (int idx = tid; idx < 49 * 32; idx += 256) {
        int n = idx >> 5, d = idx & 31;
        float a = 0.f;
        #pragma unroll
        for (int m = 0; m < 49; m++) a = fmaf(ss[n][m], vs[m][d], a);
        g_att[(size_t)gtok[n] * CC + h * HEADD + d] = a;
    }
}

// ---------------- depthwise 3x3 conv + BN ----------------
__global__ void conv_bn_kernel(const float* __restrict__ conv_w,
                               const float* __restrict__ bn_g,
                               const float* __restrict__ bn_b,
                               const float* __restrict__ bn_mean,
                               const float* __restrict__ bn_var) {
    int idx = blockIdx.x * 256 + threadIdx.x;
    if (idx >= TOKENS * CC) return;
    int c   = idx % CC;
    int tok = idx / CC;
    int b   = tok / HWD;
    int hw  = tok - b * HWD;
    int h   = hw / SIDE, w = hw - h * SIDE;
    float acc = 0.f;
    #pragma unroll
    for (int dy = 0; dy < 3; dy++) {
        int y = h + dy - 1;
        if (y < 0 || y >= SIDE) continue;
        #pragma unroll
        for (int dx = 0; dx < 3; dx++) {
            int xx = w + dx - 1;
            if (xx < 0 || xx >= SIDE) continue;
            acc = fmaf(g_seq1[(size_t)(b * HWD + y * SIDE + xx) * CC + c],
                       __ldg(&conv_w[c * 9 + dy * 3 + dx]), acc);
        }
    }
    float sc = __ldg(&bn_g[c]) * rsqrtf(__ldg(&bn_var[c]) + LN_EPS);
    g_seq2[idx] = (acc - __ldg(&bn_mean[c])) * sc + __ldg(&bn_b[c]);
}

// ---------------------------------------------------------------------------
extern "C" void kernel_launch(void* const* d_in, const int* in_sizes, int n_in,
                              void* d_out, int out_size) {
    const float* x          = (const float*)d_in[0];
    const float* ln_g       = (const float*)d_in[1];
    const float* ln_b       = (const float*)d_in[2];
    const float* qkv_w      = (const float*)d_in[3];
    const float* qkv_b      = (const float*)d_in[4];
    const float* proj_w     = (const float*)d_in[5];
    const float* proj_b     = (const float*)d_in[6];
    const float* bias_table = (const float*)d_in[7];
    const float* conv_w     = (const float*)d_in[8];
    const float* bn_g       = (const float*)d_in[9];
    const float* bn_b       = (const float*)d_in[10];
    const float* bn_mean    = (const float*)d_in[11];
    const float* bn_var     = (const float*)d_in[12];
    const float* w1         = (const float*)d_in[13];
    const float* b1         = (const float*)d_in[14];
    const float* w2         = (const float*)d_in[15];
    const float* b2         = (const float*)d_in[16];
    float* out = (float*)d_out;

    static bool attrs_set = false;
    if (!attrs_set) {
        cudaFuncSetAttribute(mma_gemm<0>, cudaFuncAttributeMaxDynamicSharedMemorySize, SMEM_BYTES);
        cudaFuncSetAttribute(mma_gemm<1>, cudaFuncAttributeMaxDynamicSharedMemorySize, SMEM_BYTES);
        cudaFuncSetAttribute(mma_gemm<2>, cudaFuncAttributeMaxDynamicSharedMemorySize, SMEM_BYTES);
        cudaFuncSetAttribute(mma_gemm<3>, cudaFuncAttributeMaxDynamicSharedMemorySize, SMEM_BYTES);
        attrs_set = true;
    }

    ln_stats_kernel<<<TOKENS / 64, 256>>>(x);
    mma_gemm<0><<<dim3(QKVN / 128, TOKENS / 128), 256, SMEM_BYTES>>>(x, qkv_w, qkv_b, ln_g, ln_b, nullptr);
    attn_kernel<<<NWIN * NHEADS, 256>>>(bias_table);
    mma_gemm<1><<<dim3(CC / 128, TOKENS / 128), 256, SMEM_BYTES>>>(x, proj_w, proj_b, nullptr, nullptr, nullptr);
    conv_bn_kernel<<<(TOKENS * CC + 255) / 256, 256>>>(conv_w, bn_g, bn_b, bn_mean, bn_var);
    mma_gemm<2><<<dim3(HIDDEN / 128, TOKENS / 128), 256, SMEM_BYTES>>>(nullptr, w1, b1, nullptr, nullptr, nullptr);
    mma_gemm<3><<<dim3(CC / 128, TOKENS / 128), 256, SMEM_BYTES>>>(nullptr, w2, b2, nullptr, nullptr, out);
}